// round 9
// baseline (speedup 1.0000x reference)
#include <cuda_runtime.h>
#include <math.h>
#include <limits.h>

// Problem constants
#define L_LAYERS 32
#define BEAM 8
#define KV2 2
#define HEADS 8
#define SEQ 1024
#define HDIM 64
#define VOCAB 50257
#define HIST 128
#define TOPK 8
#define PARTS 32
#define SEG ((VOCAB + PARTS - 1) / PARTS)   // 1571

// Derived
#define CH  (KV2*HEADS*SEQ*HDIM)        // floats per (layer, beam) chunk = 1,048,576
#define CH4 (CH/4)                      // float4 per chunk = 262,144
#define TOTAL4 (L_LAYERS*BEAM*CH4)      // 67,108,864 float4

#define SEL_BLOCKS (BEAM * PARTS)       // 256
#define GATHER_BLOCKS 4096
#define GRID (SEL_BLOCKS + GATHER_BLOCKS)
#define GSTRIDE (GATHER_BLOCKS * 256u)  // 1,048,576 threads

// Output layout (flattened tuple, all as float32)
#define OFF_SAVE 268435456
#define OFF_PROB (OFF_SAVE + BEAM*(HIST+1))
#define OFF_TBI  (OFF_PROB + BEAM)
#define OFF_MAX  (OFF_TBI + BEAM)

// Device scratch (no allocations allowed)
__device__ float g_pm[BEAM][PARTS];
__device__ float g_ps[BEAM][PARTS];
__device__ float g_pval[BEAM][PARTS][TOPK];
__device__ int   g_pidx[BEAM][PARTS][TOPK];
__device__ unsigned int g_counter = 0;   // selection fan-in
__device__ unsigned int g_ready   = 0;   // selection -> gather flag
__device__ unsigned int g_done    = 0;   // gather fan-in (reset flag)
__device__ int          g_nsrc;          // number of distinct live sources
__device__ unsigned int g_work[BEAM];    // src(3b) | dest_mask<<8

// ordered-float mapping: monotonic float -> uint32
__device__ __forceinline__ unsigned int ford(float v) {
    unsigned int u = __float_as_uint(v);
    return (u & 0x80000000u) ? ~u : (u | 0x80000000u);
}
__device__ __forceinline__ float funord(unsigned int u) {
    u = (u & 0x80000000u) ? (u & 0x7FFFFFFFu) : ~u;
    return __uint_as_float(u);
}

// ---------------------------------------------------------------------------
// Single fused kernel.
//   blocks [0, 256):       selection (partials + fan-in merge + select)
//   blocks [256, 4352):    gather, spin-wait on g_ready, compact work list,
//                          software-pipelined 4-deep loads
// ---------------------------------------------------------------------------
__global__ void __launch_bounds__(256)
fused_kernel(const float*  __restrict__ logits,
             const float*  __restrict__ prev_prob,
             const int*    __restrict__ save_id,
             const float4* __restrict__ kv,
             float*        __restrict__ out)
{
    const int tid = threadIdx.x;

    // ===================== GATHER PATH =====================
    if (blockIdx.x >= SEL_BLOCKS) {
        __shared__ unsigned int sh_work[BEAM];
        __shared__ int sh_d;

        if (tid == 0) {
            while (*(volatile unsigned int*)&g_ready == 0u) __nanosleep(64);
            __threadfence();                 // acquire
            sh_d = g_nsrc;
        }
        __syncthreads();
        if (tid < BEAM) sh_work[tid] = g_work[tid];
        __syncthreads();

        const unsigned int d = (unsigned int)sh_d;
        const int iters = 8 * (int)d;        // multiple of 4, uniform across threads

        float4* __restrict__ kvout = (float4*)out;
        const unsigned int gtid  = (blockIdx.x - SEL_BLOCKS) * 256u + tid;
        const unsigned int inner = gtid & (CH4 - 1u);   // loop-invariant
        const unsigned int ld0   = gtid >> 18;          // 0..3

        // items: ((l*d + k)*CH4 + inner); ld = ld0 + 4*it
        for (int it = 0; it < iters; it += 4) {
            float4       v[4];
            unsigned int lbase[4];
            unsigned int msk[4];
#pragma unroll
            for (int a = 0; a < 4; a++) {
                unsigned int ld = ld0 + (unsigned int)(it + a) * 4u;
                unsigned int l  = ld / d;
                unsigned int k  = ld - l * d;
                unsigned int w  = sh_work[k];
                v[a]     = __ldcs(&kv[(l * 8u + (w & 7u)) * (unsigned int)CH4 + inner]);
                lbase[a] = l * 8u * (unsigned int)CH4 + inner;
                msk[a]   = w >> 8;
            }
#pragma unroll
            for (int a = 0; a < 4; a++) {
                unsigned int m = msk[a];
                do {
                    unsigned int r = (unsigned int)__ffs(m) - 1u;
                    m &= m - 1u;
                    __stcs(&kvout[lbase[a] + r * (unsigned int)CH4], v[a]);
                } while (m);
            }
        }

        // last gather block resets flags for next graph replay
        if (tid == 0) {
            unsigned int dn = atomicAdd(&g_done, 1u);
            if (dn == (unsigned)(GATHER_BLOCKS - 1)) {
                g_done  = 0u;
                g_ready = 0u;
            }
        }
        return;
    }

    // ===================== SELECTION PATH =====================
    const int blk  = blockIdx.x;
    const int beam = blk >> 5;        // / PARTS
    const int part = blk & 31;        // % PARTS
    const float* row = logits + beam * VOCAB;

    const int start = part * SEG;
    const int end   = min(start + SEG, VOCAB);

    __shared__ float sval[256];
    __shared__ float ssum[256];
    __shared__ int   sidx[256];
    __shared__ int   stid[256];
    __shared__ int   s_last;

    // ---------------- Phase A: partials ----------------
    float lv[TOPK];
    int   li[TOPK];
#pragma unroll
    for (int i = 0; i < TOPK; i++) { lv[i] = -INFINITY; li[i] = INT_MAX; }

    float m = -INFINITY, s = 0.0f;
    for (int j = start + tid; j < end; j += 256) {
        float v = row[j];
        if (v > m) { s = s * expf(m - v) + 1.0f; m = v; }
        else       { s += expf(v - m); }
        if (v > lv[TOPK - 1]) {
            int p = TOPK - 1;
#pragma unroll
            for (int q = TOPK - 1; q > 0; q--) {
                if (v > lv[q - 1]) { lv[q] = lv[q - 1]; li[q] = li[q - 1]; p = q - 1; }
            }
            lv[p] = v; li[p] = j;
        }
    }

    // block reduce (m, s)
    sval[tid] = m; ssum[tid] = s;
    __syncthreads();
    for (int off = 128; off > 0; off >>= 1) {
        if (tid < off) {
            float m2 = sval[tid + off], s2 = ssum[tid + off];
            float m1 = sval[tid],       s1 = ssum[tid];
            float nm = fmaxf(m1, m2);
            ssum[tid] = s1 * expf(m1 - nm) + s2 * expf(m2 - nm);
            sval[tid] = nm;
        }
        __syncthreads();
    }
    if (tid == 0) { g_pm[beam][part] = sval[0]; g_ps[beam][part] = ssum[0]; }
    __syncthreads();

    // 8 rounds of block argmax over each thread's sorted-list head
    int p = 0;
    for (int r = 0; r < TOPK; r++) {
        bool valid = (p < TOPK);
        sval[tid] = valid ? lv[p] : -INFINITY;
        sidx[tid] = valid ? li[p] : INT_MAX;
        stid[tid] = tid;
        __syncthreads();
        for (int off = 128; off > 0; off >>= 1) {
            if (tid < off) {
                float v2 = sval[tid + off]; int i2 = sidx[tid + off];
                float v1 = sval[tid];       int i1 = sidx[tid];
                if (v2 > v1 || (v2 == v1 && i2 < i1)) {
                    sval[tid] = v2; sidx[tid] = i2; stid[tid] = stid[tid + off];
                }
            }
            __syncthreads();
        }
        if (tid == 0) {
            g_pval[beam][part][r] = sval[0];
            g_pidx[beam][part][r] = sidx[0];
        }
        int winner = stid[0];
        __syncthreads();
        if (tid == winner) p++;
    }

    // ---------------- fan-in: elect last selection block ----------------
    __threadfence();            // release partial writes
    if (tid == 0) {
        unsigned int done = atomicAdd(&g_counter, 1u);
        s_last = (done == (unsigned)(SEL_BLOCKS - 1));
    }
    __syncthreads();
    if (!s_last) return;
    __threadfence();            // acquire: see all partials

    // ---------------- Phase B: merge (warp w = beam w) ----------------
    __shared__ float s_cand[BEAM * TOPK];
    __shared__ int   s_cidx[BEAM * TOPK];
    __shared__ int   s_beam[BEAM];
    __shared__ int   s_tbi[BEAM];

    const int wid  = tid >> 5;
    const int lane = tid & 31;

    if (wid < BEAM) {
        const int b = wid;
        float pm = g_pm[b][lane];
        float ps = g_ps[b][lane];
        float nm = pm;
#pragma unroll
        for (int off = 16; off > 0; off >>= 1)
            nm = fmaxf(nm, __shfl_xor_sync(0xFFFFFFFFu, nm, off));
        float sc = ps * expf(pm - nm);
#pragma unroll
        for (int off = 16; off > 0; off >>= 1)
            sc += __shfl_xor_sync(0xFFFFFFFFu, sc, off);
        float base = prev_prob[b] - (nm + logf(sc));

        float mv[TOPK];
        int   mi[TOPK];
#pragma unroll
        for (int i = 0; i < TOPK; i++) {
            mv[i] = g_pval[b][lane][i];
            mi[i] = g_pidx[b][lane][i];
        }

        for (int r = 0; r < TOPK; r++) {
            float bv = -INFINITY; int bidx = INT_MAX; int bslot = 0;
#pragma unroll
            for (int i = 0; i < TOPK; i++) {
                if (mv[i] > bv || (mv[i] == bv && mi[i] < bidx)) {
                    bv = mv[i]; bidx = mi[i]; bslot = i;
                }
            }
            unsigned long long key =
                ((unsigned long long)ford(bv) << 32) |
                (unsigned long long)(0xFFFFFFFFu - (unsigned int)bidx);
            unsigned long long mk = key;
#pragma unroll
            for (int off = 16; off > 0; off >>= 1) {
                unsigned long long o = __shfl_xor_sync(0xFFFFFFFFu, mk, off);
                if (o > mk) mk = o;
            }
            float wv   = funord((unsigned int)(mk >> 32));
            int   widx = (int)(0xFFFFFFFFu - (unsigned int)(mk & 0xFFFFFFFFu));
            if (lane == 0) {
                s_cand[b * TOPK + r] = wv + base;
                s_cidx[b * TOPK + r] = widx;
            }
            if (key == mk) mv[bslot] = -INFINITY;   // pop (unique idx -> one lane)
        }
    }
    __syncthreads();

    // ---------------- Phase C: final select + compact work list ----------------
    if (tid == 0) {
        bool used[BEAM * TOPK];
#pragma unroll
        for (int c = 0; c < BEAM * TOPK; c++) used[c] = false;

        int          srcs[BEAM];
        unsigned int masks[BEAM];
        int nsrc = 0;

        for (int r = 0; r < BEAM; r++) {
            int best = -1; float bv = -INFINITY;
            for (int c = 0; c < BEAM * TOPK; c++) {
                if (!used[c] && s_cand[c] > bv) { bv = s_cand[c]; best = c; }
            }
            used[best] = true;
            int bi = best >> 3;              // source beam
            int ti = s_cidx[best];
            s_beam[r] = bi;
            s_tbi[r]  = ti;

            int k;
            for (k = 0; k < nsrc; k++) if (srcs[k] == bi) break;
            if (k == nsrc) { srcs[nsrc] = bi; masks[nsrc] = 0u; nsrc++; }
            masks[k] |= 1u << r;

            out[OFF_PROB + r] = bv;
            out[OFF_TBI + r]  = (float)ti;
        }
        out[OFF_MAX] = (float)s_tbi[0];

        for (int k = 0; k < nsrc; k++)
            g_work[k] = (unsigned int)srcs[k] | (masks[k] << 8);
        g_nsrc    = nsrc;
        g_counter = 0;                       // reset fan-in for next replay
        __threadfence();                     // release work list before flag
        atomicExch(&g_ready, 1u);            // wake gather blocks
    }
    __syncthreads();

    // new_save_id
    for (int e = tid; e < BEAM * (HIST + 1); e += blockDim.x) {
        int bn = e / (HIST + 1);
        int c  = e - bn * (HIST + 1);
        float v = (c < HIST) ? (float)save_id[s_beam[bn] * HIST + c]
                             : (float)s_tbi[bn];
        out[OFF_SAVE + e] = v;
    }
}

// ---------------------------------------------------------------------------
extern "C" void kernel_launch(void* const* d_in, const int* in_sizes, int n_in,
                              void* d_out, int out_size)
{
    const float* kv_cache  = (const float*)d_in[0];
    const float* logits    = (const float*)d_in[1];
    const int*   save_id   = (const int*)d_in[2];
    const float* prev_prob = (const float*)d_in[3];
    float* out = (float*)d_out;

    fused_kernel<<<GRID, 256>>>(logits, prev_prob, save_id,
                                (const float4*)kv_cache, out);
}

// round 11
// speedup vs baseline: 1.0004x; 1.0004x over previous
#include <cuda_runtime.h>
#include <math.h>
#include <limits.h>

// Problem constants
#define L_LAYERS 32
#define BEAM 8
#define KV2 2
#define HEADS 8
#define SEQ 1024
#define HDIM 64
#define VOCAB 50257
#define HIST 128
#define TOPK 8
#define PARTS 32
#define SEG ((VOCAB + PARTS - 1) / PARTS)   // 1571

// Derived
#define CH  (KV2*HEADS*SEQ*HDIM)        // floats per (layer, beam) chunk = 1,048,576
#define CH4 (CH/4)                      // float4 per chunk = 262,144
#define TOTAL4 (L_LAYERS*BEAM*CH4)      // 67,108,864 float4

#define SEL_BLOCKS (BEAM * PARTS)       // 256
#define GATHER_BLOCKS 4096
#define GRID (SEL_BLOCKS + GATHER_BLOCKS)
#define GSTRIDE (GATHER_BLOCKS * 256u)  // 1,048,576 threads

// Output layout (flattened tuple, all as float32)
#define OFF_SAVE 268435456
#define OFF_PROB (OFF_SAVE + BEAM*(HIST+1))
#define OFF_TBI  (OFF_PROB + BEAM)
#define OFF_MAX  (OFF_TBI + BEAM)

// Device scratch (no allocations allowed)
__device__ float g_pm[BEAM][PARTS];
__device__ float g_ps[BEAM][PARTS];
__device__ float g_pval[BEAM][PARTS][TOPK];
__device__ int   g_pidx[BEAM][PARTS][TOPK];
__device__ unsigned int g_counter = 0;   // selection fan-in
__device__ unsigned int g_ready   = 0;   // selection -> gather flag
__device__ unsigned int g_done    = 0;   // gather fan-in (reset flag)
__device__ int          g_nsrc;          // number of distinct live sources
__device__ unsigned int g_work[BEAM];    // src(3b) | dest_mask<<8

// ordered-float mapping: monotonic float -> uint32
__device__ __forceinline__ unsigned int ford(float v) {
    unsigned int u = __float_as_uint(v);
    return (u & 0x80000000u) ? ~u : (u | 0x80000000u);
}
__device__ __forceinline__ float funord(unsigned int u) {
    u = (u & 0x80000000u) ? (u & 0x7FFFFFFFu) : ~u;
    return __uint_as_float(u);
}

// ---------------------------------------------------------------------------
// Single fused kernel.
//   blocks [0, 256):       selection (partials + fan-in merge + select)
//   blocks [256, 4352):    gather, spin-wait on g_ready, compact work list,
//                          4-deep pipelined loads, k-major item enumeration
// ---------------------------------------------------------------------------
__global__ void __launch_bounds__(256, 4)
fused_kernel(const float*  __restrict__ logits,
             const float*  __restrict__ prev_prob,
             const int*    __restrict__ save_id,
             const float4* __restrict__ kv,
             float*        __restrict__ out)
{
    const int tid = threadIdx.x;

    // ===================== GATHER PATH =====================
    if (blockIdx.x >= SEL_BLOCKS) {
        __shared__ unsigned int sh_work[BEAM];
        __shared__ int sh_d;

        if (tid == 0) {
            while (*(volatile unsigned int*)&g_ready == 0u) __nanosleep(64);
            __threadfence();                 // acquire
            sh_d = g_nsrc;
        }
        __syncthreads();
        if (tid < BEAM) sh_work[tid] = g_work[tid];
        __syncthreads();

        const int iters = 8 * sh_d;          // multiple of 4, uniform across threads

        float4* __restrict__ kvout = (float4*)out;
        const unsigned int gtid  = (blockIdx.x - SEL_BLOCKS) * 256u + tid;
        const unsigned int inner = gtid & (CH4 - 1u);   // loop-invariant
        const unsigned int it0   = gtid >> 18;          // 0..3

        // k-major items: item = k*32 + l; item = it0 + 4*n, n = 0..8d-1.
        // l = item & 31, k = item >> 5 — pure bit ops, no division.
        for (int it = 0; it < iters; it += 4) {
            float4       v[4];
            unsigned int lbase[4];
            unsigned int msk[4];
#pragma unroll
            for (int a = 0; a < 4; a++) {
                unsigned int item = it0 + (unsigned int)(it + a) * 4u;
                unsigned int l    = item & 31u;
                unsigned int k    = item >> 5;
                unsigned int w    = sh_work[k];
                v[a]     = __ldcs(&kv[(l * 8u + (w & 7u)) * (unsigned int)CH4 + inner]);
                lbase[a] = l * 8u * (unsigned int)CH4 + inner;
                msk[a]   = w >> 8;
            }
#pragma unroll
            for (int a = 0; a < 4; a++) {
                unsigned int m = msk[a];
                do {
                    unsigned int r = (unsigned int)__ffs(m) - 1u;
                    m &= m - 1u;
                    __stcs(&kvout[lbase[a] + r * (unsigned int)CH4], v[a]);
                } while (m);
            }
        }

        // last gather block resets flags for next graph replay
        if (tid == 0) {
            unsigned int dn = atomicAdd(&g_done, 1u);
            if (dn == (unsigned)(GATHER_BLOCKS - 1)) {
                g_done  = 0u;
                g_ready = 0u;
            }
        }
        return;
    }

    // ===================== SELECTION PATH =====================
    const int blk  = blockIdx.x;
    const int beam = blk >> 5;        // / PARTS
    const int part = blk & 31;        // % PARTS
    const float* row = logits + beam * VOCAB;

    const int start = part * SEG;
    const int end   = min(start + SEG, VOCAB);

    __shared__ float sval[256];
    __shared__ float ssum[256];
    __shared__ int   sidx[256];
    __shared__ int   stid[256];
    __shared__ int   s_last;

    // ---------------- Phase A: partials ----------------
    float lv[TOPK];
    int   li[TOPK];
#pragma unroll
    for (int i = 0; i < TOPK; i++) { lv[i] = -INFINITY; li[i] = INT_MAX; }

    float m = -INFINITY, s = 0.0f;
    for (int j = start + tid; j < end; j += 256) {
        float v = row[j];
        if (v > m) { s = s * expf(m - v) + 1.0f; m = v; }
        else       { s += expf(v - m); }
        if (v > lv[TOPK - 1]) {
            int p = TOPK - 1;
#pragma unroll
            for (int q = TOPK - 1; q > 0; q--) {
                if (v > lv[q - 1]) { lv[q] = lv[q - 1]; li[q] = li[q - 1]; p = q - 1; }
            }
            lv[p] = v; li[p] = j;
        }
    }

    // block reduce (m, s)
    sval[tid] = m; ssum[tid] = s;
    __syncthreads();
    for (int off = 128; off > 0; off >>= 1) {
        if (tid < off) {
            float m2 = sval[tid + off], s2 = ssum[tid + off];
            float m1 = sval[tid],       s1 = ssum[tid];
            float nm = fmaxf(m1, m2);
            ssum[tid] = s1 * expf(m1 - nm) + s2 * expf(m2 - nm);
            sval[tid] = nm;
        }
        __syncthreads();
    }
    if (tid == 0) { g_pm[beam][part] = sval[0]; g_ps[beam][part] = ssum[0]; }
    __syncthreads();

    // 8 rounds of block argmax over each thread's sorted-list head
    int p = 0;
    for (int r = 0; r < TOPK; r++) {
        bool valid = (p < TOPK);
        sval[tid] = valid ? lv[p] : -INFINITY;
        sidx[tid] = valid ? li[p] : INT_MAX;
        stid[tid] = tid;
        __syncthreads();
        for (int off = 128; off > 0; off >>= 1) {
            if (tid < off) {
                float v2 = sval[tid + off]; int i2 = sidx[tid + off];
                float v1 = sval[tid];       int i1 = sidx[tid];
                if (v2 > v1 || (v2 == v1 && i2 < i1)) {
                    sval[tid] = v2; sidx[tid] = i2; stid[tid] = stid[tid + off];
                }
            }
            __syncthreads();
        }
        if (tid == 0) {
            g_pval[beam][part][r] = sval[0];
            g_pidx[beam][part][r] = sidx[0];
        }
        int winner = stid[0];
        __syncthreads();
        if (tid == winner) p++;
    }

    // ---------------- fan-in: elect last selection block ----------------
    __threadfence();            // release partial writes
    if (tid == 0) {
        unsigned int done = atomicAdd(&g_counter, 1u);
        s_last = (done == (unsigned)(SEL_BLOCKS - 1));
    }
    __syncthreads();
    if (!s_last) return;
    __threadfence();            // acquire: see all partials

    // ---------------- Phase B: merge (warp w = beam w) ----------------
    __shared__ float s_cand[BEAM * TOPK];
    __shared__ int   s_cidx[BEAM * TOPK];
    __shared__ int   s_beam[BEAM];
    __shared__ int   s_tbi[BEAM];

    const int wid  = tid >> 5;
    const int lane = tid & 31;

    if (wid < BEAM) {
        const int b = wid;
        float pm = g_pm[b][lane];
        float ps = g_ps[b][lane];
        float nm = pm;
#pragma unroll
        for (int off = 16; off > 0; off >>= 1)
            nm = fmaxf(nm, __shfl_xor_sync(0xFFFFFFFFu, nm, off));
        float sc = ps * expf(pm - nm);
#pragma unroll
        for (int off = 16; off > 0; off >>= 1)
            sc += __shfl_xor_sync(0xFFFFFFFFu, sc, off);
        float base = prev_prob[b] - (nm + logf(sc));

        float mv[TOPK];
        int   mi[TOPK];
#pragma unroll
        for (int i = 0; i < TOPK; i++) {
            mv[i] = g_pval[b][lane][i];
            mi[i] = g_pidx[b][lane][i];
        }

        for (int r = 0; r < TOPK; r++) {
            float bv = -INFINITY; int bidx = INT_MAX; int bslot = 0;
#pragma unroll
            for (int i = 0; i < TOPK; i++) {
                if (mv[i] > bv || (mv[i] == bv && mi[i] < bidx)) {
                    bv = mv[i]; bidx = mi[i]; bslot = i;
                }
            }
            unsigned long long key =
                ((unsigned long long)ford(bv) << 32) |
                (unsigned long long)(0xFFFFFFFFu - (unsigned int)bidx);
            unsigned long long mk = key;
#pragma unroll
            for (int off = 16; off > 0; off >>= 1) {
                unsigned long long o = __shfl_xor_sync(0xFFFFFFFFu, mk, off);
                if (o > mk) mk = o;
            }
            float wv   = funord((unsigned int)(mk >> 32));
            int   widx = (int)(0xFFFFFFFFu - (unsigned int)(mk & 0xFFFFFFFFu));
            if (lane == 0) {
                s_cand[b * TOPK + r] = wv + base;
                s_cidx[b * TOPK + r] = widx;
            }
            if (key == mk) mv[bslot] = -INFINITY;   // pop (unique idx -> one lane)
        }
    }
    __syncthreads();

    // ---------------- Phase C: final select + compact work list ----------------
    if (tid == 0) {
        bool used[BEAM * TOPK];
#pragma unroll
        for (int c = 0; c < BEAM * TOPK; c++) used[c] = false;

        int          srcs[BEAM];
        unsigned int masks[BEAM];
        int nsrc = 0;

        for (int r = 0; r < BEAM; r++) {
            int best = -1; float bv = -INFINITY;
            for (int c = 0; c < BEAM * TOPK; c++) {
                if (!used[c] && s_cand[c] > bv) { bv = s_cand[c]; best = c; }
            }
            used[best] = true;
            int bi = best >> 3;              // source beam
            int ti = s_cidx[best];
            s_beam[r] = bi;
            s_tbi[r]  = ti;

            int k;
            for (k = 0; k < nsrc; k++) if (srcs[k] == bi) break;
            if (k == nsrc) { srcs[nsrc] = bi; masks[nsrc] = 0u; nsrc++; }
            masks[k] |= 1u << r;

            out[OFF_PROB + r] = bv;
            out[OFF_TBI + r]  = (float)ti;
        }
        out[OFF_MAX] = (float)s_tbi[0];

        for (int k = 0; k < nsrc; k++)
            g_work[k] = (unsigned int)srcs[k] | (masks[k] << 8);
        g_nsrc    = nsrc;
        g_counter = 0;                       // reset fan-in for next replay
        __threadfence();                     // release work list before flag
        atomicExch(&g_ready, 1u);            // wake gather blocks
    }
    __syncthreads();

    // new_save_id
    for (int e = tid; e < BEAM * (HIST + 1); e += blockDim.x) {
        int bn = e / (HIST + 1);
        int c  = e - bn * (HIST + 1);
        float v = (c < HIST) ? (float)save_id[s_beam[bn] * HIST + c]
                             : (float)s_tbi[bn];
        out[OFF_SAVE + e] = v;
    }
}

// ---------------------------------------------------------------------------
extern "C" void kernel_launch(void* const* d_in, const int* in_sizes, int n_in,
                              void* d_out, int out_size)
{
    const float* kv_cache  = (const float*)d_in[0];
    const float* logits    = (const float*)d_in[1];
    const int*   save_id   = (const int*)d_in[2];
    const float* prev_prob = (const float*)d_in[3];
    float* out = (float*)d_out;

    fused_kernel<<<GRID, 256>>>(logits, prev_prob, save_id,
                                (const float4*)kv_cache, out);
}

// round 13
// speedup vs baseline: 1.0572x; 1.0568x over previous
#include <cuda_runtime.h>
#include <math.h>
#include <limits.h>

// Problem constants
#define L_LAYERS 32
#define BEAM 8
#define KV2 2
#define HEADS 8
#define SEQ 1024
#define HDIM 64
#define VOCAB 50257
#define HIST 128
#define TOPK 8
#define PARTS 32
#define SEG ((VOCAB + PARTS - 1) / PARTS)   // 1571

// Derived
#define CH  (KV2*HEADS*SEQ*HDIM)        // floats per (layer, beam) chunk = 1,048,576
#define CH4 (CH/4)                      // float4 per chunk = 262,144
#define TOTAL4 (L_LAYERS*BEAM*CH4)      // 67,108,864 float4

#define SEL_BLOCKS (BEAM * PARTS)       // 256
#define GATHER_BLOCKS 8192
#define GRID (SEL_BLOCKS + GATHER_BLOCKS)
#define GSTRIDE (GATHER_BLOCKS * 256u)  // 2,097,152 threads

// Output layout (flattened tuple, all as float32)
#define OFF_SAVE 268435456
#define OFF_PROB (OFF_SAVE + BEAM*(HIST+1))
#define OFF_TBI  (OFF_PROB + BEAM)
#define OFF_MAX  (OFF_TBI + BEAM)

// Device scratch (no allocations allowed)
__device__ float g_pm[BEAM][PARTS];
__device__ float g_ps[BEAM][PARTS];
__device__ float g_pval[BEAM][PARTS][TOPK];
__device__ int   g_pidx[BEAM][PARTS][TOPK];
__device__ unsigned int g_counter = 0;   // selection fan-in
__device__ unsigned int g_ready   = 0;   // selection -> gather flag
__device__ unsigned int g_done    = 0;   // gather fan-in (reset flag)
__device__ int          g_nsrc;          // number of distinct live sources
__device__ unsigned int g_work[BEAM];    // src(3b) | dest_mask<<8

// ordered-float mapping: monotonic float -> uint32
__device__ __forceinline__ unsigned int ford(float v) {
    unsigned int u = __float_as_uint(v);
    return (u & 0x80000000u) ? ~u : (u | 0x80000000u);
}
__device__ __forceinline__ float funord(unsigned int u) {
    u = (u & 0x80000000u) ? (u & 0x7FFFFFFFu) : ~u;
    return __uint_as_float(u);
}
// pack (value desc, idx asc) into one descending u64 key
__device__ __forceinline__ unsigned long long pkey(float v, int idx) {
    return ((unsigned long long)ford(v) << 32) |
           (unsigned long long)(0xFFFFFFFFu - (unsigned int)idx);
}
__device__ __forceinline__ float kval(unsigned long long k) { return funord((unsigned int)(k >> 32)); }
__device__ __forceinline__ int   kidx(unsigned long long k) { return (int)(0xFFFFFFFFu - (unsigned int)(k & 0xFFFFFFFFu)); }

// warp max of u64 key
__device__ __forceinline__ unsigned long long warp_max_u64(unsigned long long k) {
#pragma unroll
    for (int off = 16; off > 0; off >>= 1) {
        unsigned long long o = __shfl_xor_sync(0xFFFFFFFFu, k, off);
        if (o > k) k = o;
    }
    return k;
}
// -inf-safe (m,s) combine
__device__ __forceinline__ void ms_combine(float& m1, float& s1, float m2, float s2) {
    float nm = fmaxf(m1, m2);
    float t1 = (m1 == -INFINITY) ? 0.0f : s1 * expf(m1 - nm);
    float t2 = (m2 == -INFINITY) ? 0.0f : s2 * expf(m2 - nm);
    m1 = nm; s1 = t1 + t2;
}

// ---------------------------------------------------------------------------
// Single fused kernel.
//   blocks [0, 256):        selection (partials + fan-in merge + select)
//   blocks [256, 8448):     gather, spin-wait on g_ready, compact work list
// ---------------------------------------------------------------------------
__global__ void __launch_bounds__(256, 4)
fused_kernel(const float*  __restrict__ logits,
             const float*  __restrict__ prev_prob,
             const int*    __restrict__ save_id,
             const float4* __restrict__ kv,
             float*        __restrict__ out)
{
    const int tid = threadIdx.x;

    // ===================== GATHER PATH =====================
    if (blockIdx.x >= SEL_BLOCKS) {
        __shared__ unsigned int sh_work[BEAM];
        __shared__ int sh_d;

        if (tid == 0) {
            while (*(volatile unsigned int*)&g_ready == 0u) __nanosleep(32);
            __threadfence();                 // acquire
            sh_d = g_nsrc;
        }
        __syncthreads();
        if (tid < BEAM) sh_work[tid] = g_work[tid];
        __syncthreads();

        const int iters = 4 * sh_d;          // multiple of 4, uniform across threads

        float4* __restrict__ kvout = (float4*)out;
        const unsigned int gtid  = (blockIdx.x - SEL_BLOCKS) * 256u + tid;
        const unsigned int inner = gtid & (CH4 - 1u);   // loop-invariant
        const unsigned int it0   = gtid >> 18;          // 0..7

        // k-major items: item = k*32 + l = it0 + 8*n, n = 0..4d-1
        for (int it = 0; it < iters; it += 4) {
            float4       v[4];
            unsigned int lbase[4];
            unsigned int msk[4];
#pragma unroll
            for (int a = 0; a < 4; a++) {
                unsigned int item = it0 + (unsigned int)(it + a) * 8u;
                unsigned int l    = item & 31u;
                unsigned int k    = item >> 5;
                unsigned int w    = sh_work[k];
                v[a]     = __ldcs(&kv[(l * 8u + (w & 7u)) * (unsigned int)CH4 + inner]);
                lbase[a] = l * 8u * (unsigned int)CH4 + inner;
                msk[a]   = w >> 8;
            }
#pragma unroll
            for (int a = 0; a < 4; a++) {
                unsigned int m = msk[a];
                do {
                    unsigned int r = (unsigned int)__ffs(m) - 1u;
                    m &= m - 1u;
                    __stcs(&kvout[lbase[a] + r * (unsigned int)CH4], v[a]);
                } while (m);
            }
        }

        // last gather block resets flags for next graph replay
        if (tid == 0) {
            unsigned int dn = atomicAdd(&g_done, 1u);
            if (dn == (unsigned)(GATHER_BLOCKS - 1)) {
                g_done  = 0u;
                g_ready = 0u;
            }
        }
        return;
    }

    // ===================== SELECTION PATH =====================
    const int blk  = blockIdx.x;
    const int beam = blk >> 5;        // / PARTS
    const int part = blk & 31;        // % PARTS
    const int wid  = tid >> 5;
    const int lane = tid & 31;
    const float* row = logits + beam * VOCAB;

    const int start = part * SEG;
    const int end   = min(start + SEG, VOCAB);

    __shared__ float s_wm[8], s_ws[8];                 // per-warp (m,s)
    __shared__ unsigned long long s_wtop[8][TOPK];     // per-warp top-8 keys
    __shared__ int s_last;

    // ---------------- Phase A: thread-local pass ----------------
    float lv[TOPK];
    int   li[TOPK];
#pragma unroll
    for (int i = 0; i < TOPK; i++) { lv[i] = -INFINITY; li[i] = INT_MAX; }

    float m = -INFINITY, s = 0.0f;
    for (int j = start + tid; j < end; j += 256) {
        float v = row[j];
        if (v > m) { s = s * expf(m - v) + 1.0f; m = v; }
        else       { s += expf(v - m); }
        if (v > lv[TOPK - 1]) {
            int p = TOPK - 1;
#pragma unroll
            for (int q = TOPK - 1; q > 0; q--) {
                if (v > lv[q - 1]) { lv[q] = lv[q - 1]; li[q] = li[q - 1]; p = q - 1; }
            }
            lv[p] = v; li[p] = j;
        }
    }

    // warp (m,s) reduce
    {
        float wm = m, ws = s;
#pragma unroll
        for (int off = 16; off > 0; off >>= 1) {
            float m2 = __shfl_xor_sync(0xFFFFFFFFu, wm, off);
            float s2 = __shfl_xor_sync(0xFFFFFFFFu, ws, off);
            ms_combine(wm, ws, m2, s2);
        }
        if (lane == 0) { s_wm[wid] = wm; s_ws[wid] = ws; }
    }

    // warp top-8 via shuffle argmax (head-pointer pop)
    {
        int p = 0;
        for (int r = 0; r < TOPK; r++) {
            unsigned long long k = (p < TOPK) ? pkey(lv[p], li[p]) : 0ull;
            unsigned long long mk = warp_max_u64(k);
            if (lane == 0) s_wtop[wid][r] = mk;
            if (k == mk && p < TOPK) p++;
        }
    }
    __syncthreads();

    // warp 0: cross-warp merges
    if (wid == 0) {
        // (m,s): lanes 0..7 hold per-warp partials
        float wm = (lane < 8) ? s_wm[lane] : -INFINITY;
        float ws = (lane < 8) ? s_ws[lane] : 0.0f;
#pragma unroll
        for (int off = 16; off > 0; off >>= 1) {
            float m2 = __shfl_xor_sync(0xFFFFFFFFu, wm, off);
            float s2 = __shfl_xor_sync(0xFFFFFFFFu, ws, off);
            ms_combine(wm, ws, m2, s2);
        }
        if (lane == 0) { g_pm[beam][part] = wm; g_ps[beam][part] = ws; }

        // top-8 of 64 warp-candidates (2 per lane)
        unsigned long long c0 = s_wtop[lane >> 3][lane & 7];
        unsigned long long c1 = s_wtop[4 + (lane >> 3)][lane & 7];
        for (int r = 0; r < TOPK; r++) {
            unsigned long long k = (c0 > c1) ? c0 : c1;
            unsigned long long mk = warp_max_u64(k);
            if (lane == 0) {
                g_pval[beam][part][r] = kval(mk);
                g_pidx[beam][part][r] = kidx(mk);
            }
            if (c0 == mk) c0 = 0ull;
            else if (c1 == mk) c1 = 0ull;
        }
    }

    // ---------------- fan-in: elect last selection block ----------------
    __threadfence();            // release partial writes
    if (tid == 0) {
        unsigned int done = atomicAdd(&g_counter, 1u);
        s_last = (done == (unsigned)(SEL_BLOCKS - 1));
    }
    __syncthreads();
    if (!s_last) return;
    __threadfence();            // acquire: see all partials

    // ---------------- Phase B: merge (warp w = beam w) ----------------
    __shared__ float s_cand[BEAM * TOPK];
    __shared__ int   s_cidx[BEAM * TOPK];
    __shared__ int   s_beam[BEAM];
    __shared__ int   s_tbi[BEAM];

    if (wid < BEAM) {
        const int b = wid;
        float pm = g_pm[b][lane];
        float ps = g_ps[b][lane];
        float nm = pm;
#pragma unroll
        for (int off = 16; off > 0; off >>= 1)
            nm = fmaxf(nm, __shfl_xor_sync(0xFFFFFFFFu, nm, off));
        float sc = ps * expf(pm - nm);
#pragma unroll
        for (int off = 16; off > 0; off >>= 1)
            sc += __shfl_xor_sync(0xFFFFFFFFu, sc, off);
        float base = prev_prob[b] - (nm + logf(sc));

        float mv[TOPK];
        int   mi[TOPK];
#pragma unroll
        for (int i = 0; i < TOPK; i++) {
            mv[i] = g_pval[b][lane][i];
            mi[i] = g_pidx[b][lane][i];
        }

        for (int r = 0; r < TOPK; r++) {
            float bv = -INFINITY; int bidx = INT_MAX; int bslot = 0;
#pragma unroll
            for (int i = 0; i < TOPK; i++) {
                if (mv[i] > bv || (mv[i] == bv && mi[i] < bidx)) {
                    bv = mv[i]; bidx = mi[i]; bslot = i;
                }
            }
            unsigned long long key = pkey(bv, bidx);
            unsigned long long mk  = warp_max_u64(key);
            if (lane == 0) {
                s_cand[b * TOPK + r] = kval(mk) + base;
                s_cidx[b * TOPK + r] = kidx(mk);
            }
            if (key == mk) mv[bslot] = -INFINITY;   // pop (unique idx -> one lane)
        }
    }
    __syncthreads();

    // ---------------- Phase C: final select + compact work list ----------------
    if (tid == 0) {
        bool used[BEAM * TOPK];
#pragma unroll
        for (int c = 0; c < BEAM * TOPK; c++) used[c] = false;

        int          srcs[BEAM];
        unsigned int masks[BEAM];
        int nsrc = 0;

        for (int r = 0; r < BEAM; r++) {
            int best = -1; float bv = -INFINITY;
            for (int c = 0; c < BEAM * TOPK; c++) {
                if (!used[c] && s_cand[c] > bv) { bv = s_cand[c]; best = c; }
            }
            used[best] = true;
            int bi = best >> 3;              // source beam
            int ti = s_cidx[best];
            s_beam[r] = bi;
            s_tbi[r]  = ti;

            int k;
            for (k = 0; k < nsrc; k++) if (srcs[k] == bi) break;
            if (k == nsrc) { srcs[nsrc] = bi; masks[nsrc] = 0u; nsrc++; }
            masks[k] |= 1u << r;

            out[OFF_PROB + r] = bv;
            out[OFF_TBI + r]  = (float)ti;
        }
        out[OFF_MAX] = (float)s_tbi[0];

        for (int k = 0; k < nsrc; k++)
            g_work[k] = (unsigned int)srcs[k] | (masks[k] << 8);
        g_nsrc    = nsrc;
        g_counter = 0;                       // reset fan-in for next replay
        __threadfence();                     // release work list before flag
        atomicExch(&g_ready, 1u);            // wake gather blocks
    }
    __syncthreads();

    // new_save_id
    for (int e = tid; e < BEAM * (HIST + 1); e += blockDim.x) {
        int bn = e / (HIST + 1);
        int c  = e - bn * (HIST + 1);
        float v = (c < HIST) ? (float)save_id[s_beam[bn] * HIST + c]
                             : (float)s_tbi[bn];
        out[OFF_SAVE + e] = v;
    }
}

// ---------------------------------------------------------------------------
extern "C" void kernel_launch(void* const* d_in, const int* in_sizes, int n_in,
                              void* d_out, int out_size)
{
    const float* kv_cache  = (const float*)d_in[0];
    const float* logits    = (const float*)d_in[1];
    const int*   save_id   = (const int*)d_in[2];
    const float* prev_prob = (const float*)d_in[3];
    float* out = (float*)d_out;

    fused_kernel<<<GRID, 256>>>(logits, prev_prob, save_id,
                                (const float4*)kv_cache, out);
}